// round 6
// baseline (speedup 1.0000x reference)
#include <cuda_runtime.h>
#include <cstdint>

#define BB 16
#define FM 32
#define CC 128
#define HW 3136
#define ETA 0.1f
#define ALPHA_ 0.1f
#define THETA_ 0.1f
#define EPSF 1e-10f

typedef unsigned long long ull;

// ------------- scratch (static device globals; no allocation) -------------
__device__ float g_Ab[BB*CC*HW];        // clip(tile(symm_pad(A,2)) + eta*noise, 0)
__device__ float g_s[BB*CC];            // per-(b,c) spatial sum
__device__ float g_Kch[CC*CC*25];       // K_change [c][a][x*5+y]
__device__ float g_W2[CC*CC*25];        // conv2 weights [o][i][t]

// ---------------- packed f32x2 helpers ----------------
__device__ __forceinline__ ull pack2(float x, float y) {
    ull r; asm("mov.b64 %0, {%1,%2};" : "=l"(r) : "f"(x), "f"(y)); return r;
}
__device__ __forceinline__ void ffma2(ull& d, ull a, ull b) {
    asm("fma.rn.f32x2 %0, %1, %2, %3;" : "=l"(d) : "l"(a), "l"(b), "l"(d));
}
__device__ __forceinline__ float2 unpk(ull v) {
    float2 r; asm("mov.b64 {%0,%1}, %2;" : "=f"(r.x), "=f"(r.y) : "l"(v)); return r;
}

// symm_pad(.,2) index map on a 56 axis: 0->3, 1->2, 54->53, 55->52
__device__ __forceinline__ int m56(int h) {
    return h < 2 ? 3 - h : (h >= 54 ? 107 - h : h);
}
// pad_activations row/col map on the 60 axis (includes clobbering semantics)
__device__ __forceinline__ int m60(int r) {
    return r < 4 ? 5 - r : (r < 56 ? r - 2 : 109 - r);
}

// ---------------- kernel 1: Ab + per-channel sums (+ zero g_Kch) -----------
// 224 threads = 4 rows x 56 cols: no divides in the hot loop
__global__ void __launch_bounds__(224) k_prep(const float* __restrict__ A,
                                              const float* __restrict__ noise) {
    int bid = blockIdx.x;              // b*128 + c
    int tid = threadIdx.x;
    {   // fold K_change zeroing: 2048 blocks x 200 floats
        int z0 = bid*200;
        if (tid < 200) g_Kch[z0 + tid] = 0.f;
    }
    int b = bid >> 7, c = bid & 127;
    int f = c & 31;
    const float* Ap = A + (size_t)(b*FM + f)*HW;
    const float* Np = noise + (size_t)bid*HW;
    float* Op = g_Ab + (size_t)bid*HW;

    int h0 = tid / 56, w0 = tid - (tid/56)*56;
    int mw = m56(w0);
    float sum = 0.f;
    #pragma unroll
    for (int j = 0; j < 14; j++) {
        int h = h0 + j*4;
        int idx = h*56 + w0;
        float v = fmaxf(Ap[m56(h)*56 + mw] + ETA*Np[idx], 0.f);
        Op[idx] = v;
        sum += v;
    }
    __shared__ float red[7];
    #pragma unroll
    for (int o = 16; o; o >>= 1) sum += __shfl_xor_sync(~0u, sum, o);
    if ((tid & 31) == 0) red[tid >> 5] = sum;
    __syncthreads();
    if (tid < 32) {
        float s2 = (tid < 7) ? red[tid] : 0.f;
        #pragma unroll
        for (int o = 4; o; o >>= 1) s2 += __shfl_xor_sync(0xffu, s2, o);
        if (tid == 0) g_s[bid] = s2;
    }
}

// ---------------- K_change: crossbar-halved warp shape --------------------
// grid (b=16, cwt=2, at=4) = 128 blocks; 256 threads:
// warp = 2 winners x 16 a-pairs; block = 16 winners x 32 channels
#define CHS 34                           // channel stride (floats), 32ch + pad
#define SAB_FLOATS (6*60*CHS)            // 12240
#define SAM_ULL (2*16*56)                // double-buffered winner rows {v,v}
#define SMEM_KCH (SAB_FLOATS*4 + SAM_ULL*8)   // 63296 B

__global__ void __launch_bounds__(256) k_kch() {
    int b = blockIdx.x, cwt = blockIdx.y, at = blockIdx.z;
    int tid = threadIdx.x;
    int lane = tid & 31, wid = tid >> 5;
    int al = lane & 15;                  // a-pair -> channels (2al, 2al+1) of 32
    int cl = wid*2 + (lane >> 4);        // winner slot 0..15
    int a0 = at*32;

    extern __shared__ char smraw[];
    float* sAb  = (float*)smraw;                      // [6][60][34]
    ull*   sAm2 = (ull*)(smraw + SAB_FLOATS*4);       // [2][16][56]
    __shared__ int sC[16];

    if (tid < 16) {                      // inline winners from g_s
        int f = cwt*16 + tid;
        float best = g_s[b*CC + f]; int wr = 0;
        #pragma unroll
        for (int r = 1; r < 4; r++) {
            float v = g_s[b*CC + r*FM + f];
            if (v > best) { best = v; wr = r; }
        }
        sC[tid] = wr*FM + f;
    }
    for (int i = tid; i < SAB_FLOATS; i += 256) sAb[i] = 0.f;
    __syncthreads();

    const float* AbB = g_Ab + (size_t)b*CC*HW;

    // prologue: data rows 0..2 -> slots 0..2 (cols 2..57); slots 3..5 stay zero
    for (int r = 0; r < 3; r++)
        for (int idx = tid; idx < 32*56; idx += 256) {
            int ch = idx / 56, col = idx - ch*56;
            sAb[(r*60 + col + 2)*CHS + ch] = AbB[(size_t)(a0+ch)*HW + r*56 + col];
        }
    // am row 0 -> buffer 0
    for (int idx = tid; idx < 16*56; idx += 256) {
        int cj = idx / 56, col = idx - cj*56;
        float v = AbB[(size_t)sC[cj]*HW + col];
        sAm2[cj*56 + col] = pack2(v, v);
    }
    int myc = sC[cl];
    __syncthreads();

    ull acc[5][5];
    #pragma unroll
    for (int x = 0; x < 5; x++)
        #pragma unroll
        for (int y = 0; y < 5; y++) acc[x][y] = 0ull;

    for (int h = 0; h < 56; h++) {
        // ---- prefetch data row h+3 into regs (hidden behind compute) ----
        float pf[7];
        int prow = h + 3;
        bool pv = prow < 56;
        #pragma unroll
        for (int j = 0; j < 7; j++) {
            int idx = tid + j*256;
            int ch = idx / 56, col = idx - ch*56;
            pf[j] = pv ? AbB[(size_t)(a0+ch)*HW + prow*56 + col] : 0.f;
        }
        // ---- prefetch winner row h+1 (16x56 = 896 values) ----
        float pa[4];
        int arow = h + 1;
        #pragma unroll
        for (int j = 0; j < 4; j++) {
            int idx = tid + j*256;
            pa[j] = 0.f;
            if (arow < 56 && idx < 16*56) {
                int cj = idx / 56, co = idx - cj*56;
                pa[j] = AbB[(size_t)sC[cj]*HW + arow*56 + co];
            }
        }

        // ---- compute row h ----
        const char* rxp[5];
        #pragma unroll
        for (int x = 0; x < 5; x++) {
            int slot = (h + 8 - x) % 6;           // row h+2-x
            rxp[x] = (const char*)(sAb + slot*60*CHS + 2*al);
        }
        const ull* am = sAm2 + (size_t)(h & 1)*16*56 + cl*56;

        ull rg[5][5];
        #pragma unroll
        for (int x = 0; x < 5; x++)
            #pragma unroll
            for (int j = 0; j < 5; j++)
                rg[x][j] = *(const ull*)(rxp[x] + j*(CHS*4));

        #pragma unroll 1
        for (int wb = 0; wb < 55; wb += 5) {
            #pragma unroll
            for (int k = 0; k < 5; k++) {
                ull a = am[wb + k];
                #pragma unroll
                for (int x = 0; x < 5; x++) {
                    #pragma unroll
                    for (int y = 0; y < 5; y++)
                        ffma2(acc[x][y], a, rg[x][(k + 4 - y) % 5]);
                    rg[x][k] = *(const ull*)(rxp[x] + (wb + k + 5)*(CHS*4));
                }
            }
        }
        {   // w = 55 (ring phase k=0)
            ull a = am[55];
            #pragma unroll
            for (int x = 0; x < 5; x++)
                #pragma unroll
                for (int y = 0; y < 5; y++)
                    ffma2(acc[x][y], a, rg[x][(4 - y) % 5]);
        }

        // ---- commit prefetched data to slot (h+3)%6 (outside live window) ----
        {
            int slot = (h + 3) % 6;
            #pragma unroll
            for (int j = 0; j < 7; j++) {
                int idx = tid + j*256;
                int ch = idx / 56, col = idx - ch*56;
                sAb[(slot*60 + col + 2)*CHS + ch] = pf[j];
            }
            if (arow < 56) {
                ull* dst = sAm2 + (size_t)(arow & 1)*16*56;
                #pragma unroll
                for (int j = 0; j < 4; j++) {
                    int idx = tid + j*256;
                    if (idx < 16*56) {
                        int cj = idx / 56, co = idx - cj*56;
                        dst[cj*56 + co] = pack2(pa[j], pa[j]);
                    }
                }
            }
        }
        __syncthreads();
    }

    float* dst = g_Kch + ((size_t)myc*CC + (a0 + 2*al))*25;
    #pragma unroll
    for (int x = 0; x < 5; x++)
        #pragma unroll
        for (int y = 0; y < 5; y++) {
            float2 v = unpk(acc[x][y]);
            atomicAdd(&dst[x*5 + y],      v.x * (1.f/2048.f));
            atomicAdd(&dst[25 + x*5 + y], v.y * (1.f/2048.f));
        }
}

// ---------------- W2 = minmax(0.9*K1 + 0.1*minmax(K_change)) ---------------
__global__ void k_w2(const float* __restrict__ K) {
    int g = blockIdx.x*blockDim.x + threadIdx.x;
    if (g >= CC*CC) return;
    int o = g >> 7, i = g & 127;
    const float* kch = g_Kch + ((size_t)i*CC + o)*25;
    float v[25];
    float mn = 1e30f, mx = -1e30f;
    #pragma unroll
    for (int t = 0; t < 25; t++) { v[t] = kch[t]; mn = fminf(mn, v[t]); mx = fmaxf(mx, v[t]); }
    float inv = 1.f / (mx - mn + EPSF);
    const float* kk = K + ((size_t)o*CC + i)*25;   // K1[i][o] = K[o][i]
    float mn2 = 1e30f, mx2 = -1e30f;
    #pragma unroll
    for (int t = 0; t < 25; t++) {
        v[t] = (1.f - ALPHA_)*kk[t] + ALPHA_*((v[t] - mn)*inv);
        mn2 = fminf(mn2, v[t]); mx2 = fmaxf(mx2, v[t]);
    }
    float inv2 = 1.f / (mx2 - mn2 + EPSF);
    float* w = g_W2 + (size_t)g*25;
    #pragma unroll
    for (int t = 0; t < 25; t++) w[t] = (v[t] - mn2)*inv2;
}

// ---------------- winner-sparse conv2 + gather + output --------------------
// grid (b=16, pg=8); 256 threads = 2 i-halves x (16 f-pairs x 8 q-groups)
// 6-slot input ring + register prefetch; ONE barrier per output row
#define SIN6_ULL (6*32*61)             // 11712
#define SW_ULL   (16*801)              // 12816
#define SRED_ULL (2*128*7)             // 1792 (double-buffered)
#define SMEM_OUT ((SIN6_ULL + SW_ULL + SRED_ULL)*8)   // 210560 B

__global__ void __launch_bounds__(256) k_out(float* __restrict__ out) {
    int b = blockIdx.x, pg = blockIdx.y;
    int tid = threadIdx.x;
    int g = tid >> 7;                  // i-half: 0 -> i 0..15, 1 -> i 16..31
    int t7 = tid & 127;
    int fl = t7 >> 3;                  // f-pair 0..15 -> f = 2fl, 2fl+1
    int qg = t7 & 7;
    int q0 = qg * 7;

    extern __shared__ ull sh[];
    ull* sIn  = sh;                    // [6][32][61] duplicated {v,v}
    ull* sW   = sh + SIN6_ULL;         // [16][801] packed {w_f0, w_f1}
    ull* sRed = sh + SIN6_ULL + SW_ULL;// [2][128][7] partial acc from g=1
    __shared__ int sFm[32];
    if (tid < 32) {                    // inline winners from g_s
        float best = g_s[b*CC + tid]; int wr = 0;
        #pragma unroll
        for (int r = 1; r < 4; r++) {
            float v = g_s[b*CC + r*FM + tid];
            if (v > best) { best = v; wr = r; }
        }
        sFm[tid] = wr*FM + tid;
    }
    __syncthreads();

    for (int idx = tid; idx < 16*800; idx += 256) {
        int fp = idx / 800, rem = idx - fp*800;
        int i = rem / 25, t = rem - i*25;
        float w0 = g_W2[((size_t)sFm[2*fp  ]*CC + sFm[i])*25 + t];
        float w1 = g_W2[((size_t)sFm[2*fp+1]*CC + sFm[i])*25 + t];
        sW[fp*801 + rem] = pack2(w0, w1);
    }

    const float* AbB = g_Ab + (size_t)b*CC*HW;
    int p0 = pg * 7;

    // prologue: padded rows p0..p0+4 -> slot row%6
    #pragma unroll
    for (int r = 0; r < 5; r++) {
        int row = p0 + r, slot = row % 6, sr = m60(row);
        for (int idx = tid; idx < 32*60; idx += 256) {
            int i = idx / 60, col = idx - i*60;
            float v = AbB[(size_t)sFm[i]*HW + sr*56 + m60(col)];
            sIn[(slot*32 + i)*61 + col] = pack2(v, v);
        }
    }
    __syncthreads();

    const ull* wbase = sW + fl*801;
    int i0 = g*16;
    for (int p = p0; p < p0 + 7; p++) {
        // ---- prefetch padded row p+5 into regs ----
        float pf[8];
        int prow = p + 5;
        bool pv = prow < 60;
        int sr = pv ? m60(prow) : 0;
        #pragma unroll
        for (int j = 0; j < 8; j++) {
            int idx = tid + j*256;
            pf[j] = 0.f;
            if (pv && idx < 32*60) {
                int i = idx / 60, col = idx - i*60;
                pf[j] = AbB[(size_t)sFm[i]*HW + sr*56 + m60(col)];
            }
        }

        // ---- compute (reads slots p..p+4) ----
        ull acc[7];
        #pragma unroll
        for (int j = 0; j < 7; j++) acc[j] = 0ull;

        #pragma unroll 1
        for (int i = i0; i < i0 + 16; i++) {
            #pragma unroll
            for (int u = 0; u < 5; u++) {
                const ull* wr = wbase + i*25 + u*5;
                ull w0 = wr[0], w1 = wr[1], w2 = wr[2], w3 = wr[3], w4 = wr[4];
                const ull* rp = sIn + (((p + u) % 6)*32 + i)*61 + q0;
                #pragma unroll
                for (int cc = 0; cc < 11; cc++) {
                    ull v = rp[cc];
                    if (cc <= 6)            ffma2(acc[cc],   v, w0);
                    if (cc >= 1 && cc <= 7) ffma2(acc[cc-1], v, w1);
                    if (cc >= 2 && cc <= 8) ffma2(acc[cc-2], v, w2);
                    if (cc >= 3 && cc <= 9) ffma2(acc[cc-3], v, w3);
                    if (cc >= 4)            ffma2(acc[cc-4], v, w4);
                }
            }
        }

        // ---- commit prefetched row to slot (p+5)%6 (outside live window) ----
        if (pv) {
            int slot = prow % 6;
            #pragma unroll
            for (int j = 0; j < 8; j++) {
                int idx = tid + j*256;
                if (idx < 32*60) {
                    int i = idx / 60, col = idx - i*60;
                    sIn[(slot*32 + i)*61 + col] = pack2(pf[j], pf[j]);
                }
            }
        }
        // ---- partial handoff (double-buffered by p&1) ----
        ull* red = sRed + (size_t)(p & 1)*128*7;
        if (g == 1) {
            #pragma unroll
            for (int j = 0; j < 7; j++) red[t7*7 + j] = acc[j];
        }
        __syncthreads();
        if (g == 0) {
            int f0 = 2*fl, f1 = f0 + 1;
            const float* a0r = AbB + (size_t)sFm[f0]*HW + p*56 + q0;
            const float* a1r = AbB + (size_t)sFm[f1]*HW + p*56 + q0;
            float* o0 = out + ((size_t)(b*FM + f0)*56 + p)*56 + q0;
            float* o1 = out + ((size_t)(b*FM + f1)*56 + p)*56 + q0;
            #pragma unroll
            for (int j = 0; j < 7; j++) {
                float2 v = unpk(acc[j]);
                float2 r = unpk(red[t7*7 + j]);
                o0[j] = a0r[j] + THETA_ * ((v.x + r.x) * (1.f/32.f));
                o1[j] = a1r[j] + THETA_ * ((v.y + r.y) * (1.f/32.f));
            }
        }
    }
}

// ---------------- launch ----------------
extern "C" void kernel_launch(void* const* d_in, const int* in_sizes, int n_in,
                              void* d_out, int out_size) {
    const float* A     = (const float*)d_in[0];
    const float* K     = (const float*)d_in[1];
    const float* noise = (const float*)d_in[2];
    float* out = (float*)d_out;

    k_prep<<<BB*CC, 224>>>(A, noise);

    cudaFuncSetAttribute(k_kch, cudaFuncAttributeMaxDynamicSharedMemorySize, SMEM_KCH);
    k_kch<<<dim3(BB, 2, 4), 256, SMEM_KCH>>>();

    k_w2<<<128, 128>>>(K);

    cudaFuncSetAttribute(k_out, cudaFuncAttributeMaxDynamicSharedMemorySize, SMEM_OUT);
    k_out<<<dim3(BB, 8), 256, SMEM_OUT>>>(out);
}

// round 7
// speedup vs baseline: 1.0712x; 1.0712x over previous
#include <cuda_runtime.h>
#include <cstdint>

#define BB 16
#define FM 32
#define CC 128
#define HW 3136
#define ETA 0.1f
#define ALPHA_ 0.1f
#define THETA_ 0.1f
#define EPSF 1e-10f

typedef unsigned long long ull;

// ------------- scratch (static device globals; no allocation) -------------
__device__ float g_Ab[BB*CC*HW];        // clip(tile(symm_pad(A,2)) + eta*noise, 0)
__device__ float g_s[BB*CC];            // per-(b,c) spatial sum
__device__ float g_Kch[CC*CC*25];       // K_change [c][a][x*5+y]
__device__ float g_W2[CC*CC*25];        // conv2 weights [o][i][t]

// ---------------- packed f32x2 helpers ----------------
__device__ __forceinline__ ull pack2(float x, float y) {
    ull r; asm("mov.b64 %0, {%1,%2};" : "=l"(r) : "f"(x), "f"(y)); return r;
}
__device__ __forceinline__ void ffma2(ull& d, ull a, ull b) {
    asm("fma.rn.f32x2 %0, %1, %2, %3;" : "=l"(d) : "l"(a), "l"(b), "l"(d));
}
__device__ __forceinline__ float2 unpk(ull v) {
    float2 r; asm("mov.b64 {%0,%1}, %2;" : "=f"(r.x), "=f"(r.y) : "l"(v)); return r;
}

// symm_pad(.,2) index map on a 56 axis: 0->3, 1->2, 54->53, 55->52
__device__ __forceinline__ int m56(int h) {
    return h < 2 ? 3 - h : (h >= 54 ? 107 - h : h);
}
// pad_activations row/col map on the 60 axis (includes clobbering semantics)
__device__ __forceinline__ int m60(int r) {
    return r < 4 ? 5 - r : (r < 56 ? r - 2 : 109 - r);
}

// ---------------- kernel 1: Ab + per-channel sums (+ zero g_Kch) -----------
// 224 threads = 4 rows x 56 cols: no divides in the hot loop
__global__ void __launch_bounds__(224) k_prep(const float* __restrict__ A,
                                              const float* __restrict__ noise) {
    int bid = blockIdx.x;              // b*128 + c
    int tid = threadIdx.x;
    {   // fold K_change zeroing: 2048 blocks x 200 floats
        int z0 = bid*200;
        if (tid < 200) g_Kch[z0 + tid] = 0.f;
    }
    int b = bid >> 7, c = bid & 127;
    int f = c & 31;
    const float* Ap = A + (size_t)(b*FM + f)*HW;
    const float* Np = noise + (size_t)bid*HW;
    float* Op = g_Ab + (size_t)bid*HW;

    int h0 = tid / 56, w0 = tid - (tid/56)*56;
    int mw = m56(w0);
    float sum = 0.f;
    #pragma unroll
    for (int j = 0; j < 14; j++) {
        int h = h0 + j*4;
        int idx = h*56 + w0;
        float v = fmaxf(Ap[m56(h)*56 + mw] + ETA*Np[idx], 0.f);
        Op[idx] = v;
        sum += v;
    }
    __shared__ float red[7];
    #pragma unroll
    for (int o = 16; o; o >>= 1) sum += __shfl_xor_sync(~0u, sum, o);
    if ((tid & 31) == 0) red[tid >> 5] = sum;
    __syncthreads();
    if (tid < 32) {
        float s2 = (tid < 7) ? red[tid] : 0.f;
        #pragma unroll
        for (int o = 4; o; o >>= 1) s2 += __shfl_xor_sync(0xffu, s2, o);
        if (tid == 0) g_s[bid] = s2;
    }
}

// ---------------- K_change: crossbar-halved warp shape --------------------
// grid (b=16, cwt=2, at=4) = 128 blocks; 256 threads:
// warp = 2 winners x 16 a-pairs; block = 16 winners x 32 channels
#define CHS 34                           // channel stride (floats), 32ch + pad
#define SAB_FLOATS (6*60*CHS)            // 12240
#define SAM_ULL (2*16*56)                // double-buffered winner rows {v,v}
#define SMEM_KCH (SAB_FLOATS*4 + SAM_ULL*8)   // 63296 B

__global__ void __launch_bounds__(256) k_kch() {
    int b = blockIdx.x, cwt = blockIdx.y, at = blockIdx.z;
    int tid = threadIdx.x;
    int lane = tid & 31, wid = tid >> 5;
    int al = lane & 15;                  // a-pair -> channels (2al, 2al+1) of 32
    int cl = wid*2 + (lane >> 4);        // winner slot 0..15
    int a0 = at*32;

    extern __shared__ char smraw[];
    float* sAb  = (float*)smraw;                      // [6][60][34]
    ull*   sAm2 = (ull*)(smraw + SAB_FLOATS*4);       // [2][16][56]
    __shared__ int sC[16];

    if (tid < 16) {                      // inline winners from g_s
        int f = cwt*16 + tid;
        float best = g_s[b*CC + f]; int wr = 0;
        #pragma unroll
        for (int r = 1; r < 4; r++) {
            float v = g_s[b*CC + r*FM + f];
            if (v > best) { best = v; wr = r; }
        }
        sC[tid] = wr*FM + f;
    }
    for (int i = tid; i < SAB_FLOATS; i += 256) sAb[i] = 0.f;
    __syncthreads();

    const float* AbB = g_Ab + (size_t)b*CC*HW;

    // prologue: data rows 0..2 -> slots 0..2 (cols 2..57); slots 3..5 stay zero
    for (int r = 0; r < 3; r++)
        for (int idx = tid; idx < 32*56; idx += 256) {
            int ch = idx / 56, col = idx - ch*56;
            sAb[(r*60 + col + 2)*CHS + ch] = AbB[(size_t)(a0+ch)*HW + r*56 + col];
        }
    // am row 0 -> buffer 0
    for (int idx = tid; idx < 16*56; idx += 256) {
        int cj = idx / 56, col = idx - cj*56;
        float v = AbB[(size_t)sC[cj]*HW + col];
        sAm2[cj*56 + col] = pack2(v, v);
    }
    int myc = sC[cl];
    __syncthreads();

    ull acc[5][5];
    #pragma unroll
    for (int x = 0; x < 5; x++)
        #pragma unroll
        for (int y = 0; y < 5; y++) acc[x][y] = 0ull;

    for (int h = 0; h < 56; h++) {
        // ---- prefetch data row h+3 into regs (hidden behind compute) ----
        float pf[7];
        int prow = h + 3;
        bool pv = prow < 56;
        #pragma unroll
        for (int j = 0; j < 7; j++) {
            int idx = tid + j*256;
            int ch = idx / 56, col = idx - ch*56;
            pf[j] = pv ? AbB[(size_t)(a0+ch)*HW + prow*56 + col] : 0.f;
        }
        // ---- prefetch winner row h+1 (16x56 = 896 values) ----
        float pa[4];
        int arow = h + 1;
        #pragma unroll
        for (int j = 0; j < 4; j++) {
            int idx = tid + j*256;
            pa[j] = 0.f;
            if (arow < 56 && idx < 16*56) {
                int cj = idx / 56, co = idx - cj*56;
                pa[j] = AbB[(size_t)sC[cj]*HW + arow*56 + co];
            }
        }

        // ---- compute row h ----
        const char* rxp[5];
        #pragma unroll
        for (int x = 0; x < 5; x++) {
            int slot = (h + 8 - x) % 6;           // row h+2-x
            rxp[x] = (const char*)(sAb + slot*60*CHS + 2*al);
        }
        const ull* am = sAm2 + (size_t)(h & 1)*16*56 + cl*56;

        ull rg[5][5];
        #pragma unroll
        for (int x = 0; x < 5; x++)
            #pragma unroll
            for (int j = 0; j < 5; j++)
                rg[x][j] = *(const ull*)(rxp[x] + j*(CHS*4));

        #pragma unroll 1
        for (int wb = 0; wb < 55; wb += 5) {
            #pragma unroll
            for (int k = 0; k < 5; k++) {
                ull a = am[wb + k];
                #pragma unroll
                for (int x = 0; x < 5; x++) {
                    #pragma unroll
                    for (int y = 0; y < 5; y++)
                        ffma2(acc[x][y], a, rg[x][(k + 4 - y) % 5]);
                    rg[x][k] = *(const ull*)(rxp[x] + (wb + k + 5)*(CHS*4));
                }
            }
        }
        {   // w = 55 (ring phase k=0)
            ull a = am[55];
            #pragma unroll
            for (int x = 0; x < 5; x++)
                #pragma unroll
                for (int y = 0; y < 5; y++)
                    ffma2(acc[x][y], a, rg[x][(4 - y) % 5]);
        }

        // ---- commit prefetched data to slot (h+3)%6 (outside live window) ----
        {
            int slot = (h + 3) % 6;
            #pragma unroll
            for (int j = 0; j < 7; j++) {
                int idx = tid + j*256;
                int ch = idx / 56, col = idx - ch*56;
                sAb[(slot*60 + col + 2)*CHS + ch] = pf[j];
            }
            if (arow < 56) {
                ull* dst = sAm2 + (size_t)(arow & 1)*16*56;
                #pragma unroll
                for (int j = 0; j < 4; j++) {
                    int idx = tid + j*256;
                    if (idx < 16*56) {
                        int cj = idx / 56, co = idx - cj*56;
                        dst[cj*56 + co] = pack2(pa[j], pa[j]);
                    }
                }
            }
        }
        __syncthreads();
    }

    float* dst = g_Kch + ((size_t)myc*CC + (a0 + 2*al))*25;
    #pragma unroll
    for (int x = 0; x < 5; x++)
        #pragma unroll
        for (int y = 0; y < 5; y++) {
            float2 v = unpk(acc[x][y]);
            atomicAdd(&dst[x*5 + y],      v.x * (1.f/2048.f));
            atomicAdd(&dst[25 + x*5 + y], v.y * (1.f/2048.f));
        }
}

// ---------------- W2 = minmax(0.9*K1 + 0.1*minmax(K_change)) ---------------
__global__ void k_w2(const float* __restrict__ K) {
    int g = blockIdx.x*blockDim.x + threadIdx.x;
    if (g >= CC*CC) return;
    int o = g >> 7, i = g & 127;
    const float* kch = g_Kch + ((size_t)i*CC + o)*25;
    float v[25];
    float mn = 1e30f, mx = -1e30f;
    #pragma unroll
    for (int t = 0; t < 25; t++) { v[t] = kch[t]; mn = fminf(mn, v[t]); mx = fmaxf(mx, v[t]); }
    float inv = 1.f / (mx - mn + EPSF);
    const float* kk = K + ((size_t)o*CC + i)*25;   // K1[i][o] = K[o][i]
    float mn2 = 1e30f, mx2 = -1e30f;
    #pragma unroll
    for (int t = 0; t < 25; t++) {
        v[t] = (1.f - ALPHA_)*kk[t] + ALPHA_*((v[t] - mn)*inv);
        mn2 = fminf(mn2, v[t]); mx2 = fmaxf(mx2, v[t]);
    }
    float inv2 = 1.f / (mx2 - mn2 + EPSF);
    float* w = g_W2 + (size_t)g*25;
    #pragma unroll
    for (int t = 0; t < 25; t++) w[t] = (v[t] - mn2)*inv2;
}

// ---------------- winner-sparse conv2 + gather + output --------------------
// grid (b=16, pg=8); 512 threads = 4 i-quarters x (16 f-pairs x 8 q-groups)
// 6-slot ring + register prefetch; 4 warps/SMSP to hide LDS latency
#define SIN6_ULL (6*32*61)             // 11712
#define SW_ULL   (16*801)              // 12816
#define SRED_ULL (3*128*7)             // 2688
#define SMEM_OUT ((SIN6_ULL + SW_ULL + SRED_ULL)*8)   // 217728 B

__global__ void __launch_bounds__(512) k_out(float* __restrict__ out) {
    int b = blockIdx.x, pg = blockIdx.y;
    int tid = threadIdx.x;
    int g = tid >> 7;                  // i-quarter: i in [8g, 8g+8)
    int t7 = tid & 127;
    int fl = t7 >> 3;                  // f-pair 0..15 -> f = 2fl, 2fl+1
    int qg = t7 & 7;
    int q0 = qg * 7;

    extern __shared__ ull sh[];
    ull* sIn  = sh;                    // [6][32][61] duplicated {v,v}
    ull* sW   = sh + SIN6_ULL;         // [16][801] packed {w_f0, w_f1}
    ull* sRed = sh + SIN6_ULL + SW_ULL;// [3][128][7] partials from g=1..3
    __shared__ int sFm[32];
    if (tid < 32) {                    // inline winners from g_s
        float best = g_s[b*CC + tid]; int wr = 0;
        #pragma unroll
        for (int r = 1; r < 4; r++) {
            float v = g_s[b*CC + r*FM + tid];
            if (v > best) { best = v; wr = r; }
        }
        sFm[tid] = wr*FM + tid;
    }
    __syncthreads();

    for (int idx = tid; idx < 16*800; idx += 512) {
        int fp = idx / 800, rem = idx - fp*800;
        int i = rem / 25, t = rem - i*25;
        float w0 = g_W2[((size_t)sFm[2*fp  ]*CC + sFm[i])*25 + t];
        float w1 = g_W2[((size_t)sFm[2*fp+1]*CC + sFm[i])*25 + t];
        sW[fp*801 + rem] = pack2(w0, w1);
    }

    const float* AbB = g_Ab + (size_t)b*CC*HW;
    int p0 = pg * 7;

    // prologue: padded rows p0..p0+4 -> slot row%6
    #pragma unroll
    for (int r = 0; r < 5; r++) {
        int row = p0 + r, slot = row % 6, sr = m60(row);
        for (int idx = tid; idx < 32*60; idx += 512) {
            int i = idx / 60, col = idx - i*60;
            float v = AbB[(size_t)sFm[i]*HW + sr*56 + m60(col)];
            sIn[(slot*32 + i)*61 + col] = pack2(v, v);
        }
    }
    __syncthreads();

    const ull* wbase = sW + fl*801;
    int i0 = g*8;
    for (int p = p0; p < p0 + 7; p++) {
        // ---- prefetch padded row p+5 into regs ----
        float pf[4];
        int prow = p + 5;
        bool pv = prow < 60;
        int sr = pv ? m60(prow) : 0;
        #pragma unroll
        for (int j = 0; j < 4; j++) {
            int idx = tid + j*512;
            pf[j] = 0.f;
            if (pv && idx < 32*60) {
                int i = idx / 60, col = idx - i*60;
                pf[j] = AbB[(size_t)sFm[i]*HW + sr*56 + m60(col)];
            }
        }

        // ---- compute (reads slots p..p+4), i-quarter ----
        ull acc[7];
        #pragma unroll
        for (int j = 0; j < 7; j++) acc[j] = 0ull;

        #pragma unroll 1
        for (int i = i0; i < i0 + 8; i++) {
            #pragma unroll
            for (int u = 0; u < 5; u++) {
                const ull* wr = wbase + i*25 + u*5;
                ull w0 = wr[0], w1 = wr[1], w2 = wr[2], w3 = wr[3], w4 = wr[4];
                const ull* rp = sIn + (((p + u) % 6)*32 + i)*61 + q0;
                #pragma unroll
                for (int cc = 0; cc < 11; cc++) {
                    ull v = rp[cc];
                    if (cc <= 6)            ffma2(acc[cc],   v, w0);
                    if (cc >= 1 && cc <= 7) ffma2(acc[cc-1], v, w1);
                    if (cc >= 2 && cc <= 8) ffma2(acc[cc-2], v, w2);
                    if (cc >= 3 && cc <= 9) ffma2(acc[cc-3], v, w3);
                    if (cc >= 4)            ffma2(acc[cc-4], v, w4);
                }
            }
        }

        // ---- commit prefetched row to slot (p+5)%6 (outside live window) ----
        if (pv) {
            int slot = prow % 6;
            #pragma unroll
            for (int j = 0; j < 4; j++) {
                int idx = tid + j*512;
                if (idx < 32*60) {
                    int i = idx / 60, col = idx - i*60;
                    sIn[(slot*32 + i)*61 + col] = pack2(pf[j], pf[j]);
                }
            }
        }
        // ---- partial handoff: quarters 1..3 write, quarter 0 combines ----
        if (g != 0) {
            ull* red = sRed + (size_t)(g - 1)*128*7 + t7*7;
            #pragma unroll
            for (int j = 0; j < 7; j++) red[j] = acc[j];
        }
        __syncthreads();
        if (g == 0) {
            int f0 = 2*fl, f1 = f0 + 1;
            const float* a0r = AbB + (size_t)sFm[f0]*HW + p*56 + q0;
            const float* a1r = AbB + (size_t)sFm[f1]*HW + p*56 + q0;
            float* o0 = out + ((size_t)(b*FM + f0)*56 + p)*56 + q0;
            float* o1 = out + ((size_t)(b*FM + f1)*56 + p)*56 + q0;
            #pragma unroll
            for (int j = 0; j < 7; j++) {
                float2 v = unpk(acc[j]);
                #pragma unroll
                for (int q = 0; q < 3; q++) {
                    float2 r = unpk(sRed[(size_t)q*128*7 + t7*7 + j]);
                    v.x += r.x; v.y += r.y;
                }
                o0[j] = a0r[j] + THETA_ * (v.x * (1.f/32.f));
                o1[j] = a1r[j] + THETA_ * (v.y * (1.f/32.f));
            }
        }
        __syncthreads();    // sRed reusable next p
    }
}

// ---------------- launch ----------------
extern "C" void kernel_launch(void* const* d_in, const int* in_sizes, int n_in,
                              void* d_out, int out_size) {
    const float* A     = (const float*)d_in[0];
    const float* K     = (const float*)d_in[1];
    const float* noise = (const float*)d_in[2];
    float* out = (float*)d_out;

    k_prep<<<BB*CC, 224>>>(A, noise);

    cudaFuncSetAttribute(k_kch, cudaFuncAttributeMaxDynamicSharedMemorySize, SMEM_KCH);
    k_kch<<<dim3(BB, 2, 4), 256, SMEM_KCH>>>();

    k_w2<<<128, 128>>>(K);

    cudaFuncSetAttribute(k_out, cudaFuncAttributeMaxDynamicSharedMemorySize, SMEM_OUT);
    k_out<<<dim3(BB, 8), 512, SMEM_OUT>>>(out);
}

// round 8
// speedup vs baseline: 1.0717x; 1.0005x over previous
#include <cuda_runtime.h>
#include <cstdint>

#define BB 16
#define FM 32
#define CC 128
#define HW 3136
#define ETA 0.1f
#define ALPHA_ 0.1f
#define THETA_ 0.1f
#define EPSF 1e-10f

typedef unsigned long long ull;

// ------------- scratch (static device globals; no allocation) -------------
__device__ float g_Ab[BB*CC*HW];        // clip(tile(symm_pad(A,2)) + eta*noise, 0)
__device__ float g_s[BB*CC];            // per-(b,c) spatial sum
__device__ float g_Kch[CC*CC*25];       // K_change [c][a][x*5+y]
__device__ float g_W2[CC*CC*25];        // conv2 weights [o][i][t]

// ---------------- packed f32x2 helpers ----------------
__device__ __forceinline__ ull pack2(float x, float y) {
    ull r; asm("mov.b64 %0, {%1,%2};" : "=l"(r) : "f"(x), "f"(y)); return r;
}
__device__ __forceinline__ void ffma2(ull& d, ull a, ull b) {
    asm("fma.rn.f32x2 %0, %1, %2, %3;" : "=l"(d) : "l"(a), "l"(b), "l"(d));
}
__device__ __forceinline__ float2 unpk(ull v) {
    float2 r; asm("mov.b64 {%0,%1}, %2;" : "=f"(r.x), "=f"(r.y) : "l"(v)); return r;
}

// symm_pad(.,2) index map on a 56 axis: 0->3, 1->2, 54->53, 55->52
__device__ __forceinline__ int m56(int h) {
    return h < 2 ? 3 - h : (h >= 54 ? 107 - h : h);
}
// pad_activations row/col map on the 60 axis (includes clobbering semantics)
__device__ __forceinline__ int m60(int r) {
    return r < 4 ? 5 - r : (r < 56 ? r - 2 : 109 - r);
}

// ---------------- kernel 1: Ab + per-channel sums (+ zero g_Kch) -----------
__global__ void __launch_bounds__(224) k_prep(const float* __restrict__ A,
                                              const float* __restrict__ noise) {
    int bid = blockIdx.x;              // b*128 + c
    int tid = threadIdx.x;
    {   // fold K_change zeroing: 2048 blocks x 200 floats
        int z0 = bid*200;
        if (tid < 200) g_Kch[z0 + tid] = 0.f;
    }
    int b = bid >> 7, c = bid & 127;
    int f = c & 31;
    const float* Ap = A + (size_t)(b*FM + f)*HW;
    const float* Np = noise + (size_t)bid*HW;
    float* Op = g_Ab + (size_t)bid*HW;

    int h0 = tid / 56, w0 = tid - (tid/56)*56;
    int mw = m56(w0);
    float sum = 0.f;
    #pragma unroll
    for (int j = 0; j < 14; j++) {
        int h = h0 + j*4;
        int idx = h*56 + w0;
        float v = fmaxf(Ap[m56(h)*56 + mw] + ETA*Np[idx], 0.f);
        Op[idx] = v;
        sum += v;
    }
    __shared__ float red[7];
    #pragma unroll
    for (int o = 16; o; o >>= 1) sum += __shfl_xor_sync(~0u, sum, o);
    if ((tid & 31) == 0) red[tid >> 5] = sum;
    __syncthreads();
    if (tid < 32) {
        float s2 = (tid < 7) ? red[tid] : 0.f;
        #pragma unroll
        for (int o = 4; o; o >>= 1) s2 += __shfl_xor_sync(0xffu, s2, o);
        if (tid == 0) g_s[bid] = s2;
    }
}

// ---------------- K_change: crossbar-halved warp shape --------------------
#define CHS 34
#define SAB_FLOATS (6*60*CHS)            // 12240
#define SAM_ULL (2*16*56)
#define SMEM_KCH (SAB_FLOATS*4 + SAM_ULL*8)   // 63296 B

__global__ void __launch_bounds__(256) k_kch() {
    int b = blockIdx.x, cwt = blockIdx.y, at = blockIdx.z;
    int tid = threadIdx.x;
    int lane = tid & 31, wid = tid >> 5;
    int al = lane & 15;
    int cl = wid*2 + (lane >> 4);
    int a0 = at*32;

    extern __shared__ char smraw[];
    float* sAb  = (float*)smraw;                      // [6][60][34]
    ull*   sAm2 = (ull*)(smraw + SAB_FLOATS*4);       // [2][16][56]
    __shared__ int sC[16];

    if (tid < 16) {
        int f = cwt*16 + tid;
        float best = g_s[b*CC + f]; int wr = 0;
        #pragma unroll
        for (int r = 1; r < 4; r++) {
            float v = g_s[b*CC + r*FM + f];
            if (v > best) { best = v; wr = r; }
        }
        sC[tid] = wr*FM + f;
    }
    for (int i = tid; i < SAB_FLOATS; i += 256) sAb[i] = 0.f;
    __syncthreads();

    const float* AbB = g_Ab + (size_t)b*CC*HW;

    for (int r = 0; r < 3; r++)
        for (int idx = tid; idx < 32*56; idx += 256) {
            int ch = idx / 56, col = idx - ch*56;
            sAb[(r*60 + col + 2)*CHS + ch] = AbB[(size_t)(a0+ch)*HW + r*56 + col];
        }
    for (int idx = tid; idx < 16*56; idx += 256) {
        int cj = idx / 56, col = idx - cj*56;
        float v = AbB[(size_t)sC[cj]*HW + col];
        sAm2[cj*56 + col] = pack2(v, v);
    }
    int myc = sC[cl];
    __syncthreads();

    ull acc[5][5];
    #pragma unroll
    for (int x = 0; x < 5; x++)
        #pragma unroll
        for (int y = 0; y < 5; y++) acc[x][y] = 0ull;

    for (int h = 0; h < 56; h++) {
        float pf[7];
        int prow = h + 3;
        bool pv = prow < 56;
        #pragma unroll
        for (int j = 0; j < 7; j++) {
            int idx = tid + j*256;
            int ch = idx / 56, col = idx - ch*56;
            pf[j] = pv ? AbB[(size_t)(a0+ch)*HW + prow*56 + col] : 0.f;
        }
        float pa[4];
        int arow = h + 1;
        #pragma unroll
        for (int j = 0; j < 4; j++) {
            int idx = tid + j*256;
            pa[j] = 0.f;
            if (arow < 56 && idx < 16*56) {
                int cj = idx / 56, co = idx - cj*56;
                pa[j] = AbB[(size_t)sC[cj]*HW + arow*56 + co];
            }
        }

        const char* rxp[5];
        #pragma unroll
        for (int x = 0; x < 5; x++) {
            int slot = (h + 8 - x) % 6;
            rxp[x] = (const char*)(sAb + slot*60*CHS + 2*al);
        }
        const ull* am = sAm2 + (size_t)(h & 1)*16*56 + cl*56;

        ull rg[5][5];
        #pragma unroll
        for (int x = 0; x < 5; x++)
            #pragma unroll
            for (int j = 0; j < 5; j++)
                rg[x][j] = *(const ull*)(rxp[x] + j*(CHS*4));

        #pragma unroll 1
        for (int wb = 0; wb < 55; wb += 5) {
            #pragma unroll
            for (int k = 0; k < 5; k++) {
                ull a = am[wb + k];
                #pragma unroll
                for (int x = 0; x < 5; x++) {
                    #pragma unroll
                    for (int y = 0; y < 5; y++)
                        ffma2(acc[x][y], a, rg[x][(k + 4 - y) % 5]);
                    rg[x][k] = *(const ull*)(rxp[x] + (wb + k + 5)*(CHS*4));
                }
            }
        }
        {
            ull a = am[55];
            #pragma unroll
            for (int x = 0; x < 5; x++)
                #pragma unroll
                for (int y = 0; y < 5; y++)
                    ffma2(acc[x][y], a, rg[x][(4 - y) % 5]);
        }

        {
            int slot = (h + 3) % 6;
            #pragma unroll
            for (int j = 0; j < 7; j++) {
                int idx = tid + j*256;
                int ch = idx / 56, col = idx - ch*56;
                sAb[(slot*60 + col + 2)*CHS + ch] = pf[j];
            }
            if (arow < 56) {
                ull* dst = sAm2 + (size_t)(arow & 1)*16*56;
                #pragma unroll
                for (int j = 0; j < 4; j++) {
                    int idx = tid + j*256;
                    if (idx < 16*56) {
                        int cj = idx / 56, co = idx - cj*56;
                        dst[cj*56 + co] = pack2(pa[j], pa[j]);
                    }
                }
            }
        }
        __syncthreads();
    }

    float* dst = g_Kch + ((size_t)myc*CC + (a0 + 2*al))*25;
    #pragma unroll
    for (int x = 0; x < 5; x++)
        #pragma unroll
        for (int y = 0; y < 5; y++) {
            float2 v = unpk(acc[x][y]);
            atomicAdd(&dst[x*5 + y],      v.x * (1.f/2048.f));
            atomicAdd(&dst[25 + x*5 + y], v.y * (1.f/2048.f));
        }
}

// ---------------- W2 = minmax(0.9*K1 + 0.1*minmax(K_change)) ---------------
__global__ void k_w2(const float* __restrict__ K) {
    int g = blockIdx.x*blockDim.x + threadIdx.x;
    if (g >= CC*CC) return;
    int o = g >> 7, i = g & 127;
    const float* kch = g_Kch + ((size_t)i*CC + o)*25;
    float v[25];
    float mn = 1e30f, mx = -1e30f;
    #pragma unroll
    for (int t = 0; t < 25; t++) { v[t] = kch[t]; mn = fminf(mn, v[t]); mx = fmaxf(mx, v[t]); }
    float inv = 1.f / (mx - mn + EPSF);
    const float* kk = K + ((size_t)o*CC + i)*25;   // K1[i][o] = K[o][i]
    float mn2 = 1e30f, mx2 = -1e30f;
    #pragma unroll
    for (int t = 0; t < 25; t++) {
        v[t] = (1.f - ALPHA_)*kk[t] + ALPHA_*((v[t] - mn)*inv);
        mn2 = fminf(mn2, v[t]); mx2 = fmaxf(mx2, v[t]);
    }
    float inv2 = 1.f / (mx2 - mn2 + EPSF);
    float* w = g_W2 + (size_t)g*25;
    #pragma unroll
    for (int t = 0; t < 25; t++) w[t] = (v[t] - mn2)*inv2;
}

// ---------------- winner-sparse conv2 + gather + output --------------------
// grid (b=16, pg=8); 512 threads = 4 i-quarters x (16 f-pairs x 8 q-groups)
// explicit 2-buffer software pipeline over 40 (i,u) stages
#define SIN6_ULL (6*32*61)             // 11712
#define SW_ULL   (16*801)              // 12816
#define SRED_ULL (3*128*7)             // 2688
#define SMEM_OUT ((SIN6_ULL + SW_ULL + SRED_ULL)*8)   // 217728 B

__global__ void __launch_bounds__(512) k_out(float* __restrict__ out) {
    int b = blockIdx.x, pg = blockIdx.y;
    int tid = threadIdx.x;
    int g = tid >> 7;                  // i-quarter: i in [8g, 8g+8)
    int t7 = tid & 127;
    int fl = t7 >> 3;
    int qg = t7 & 7;
    int q0 = qg * 7;

    extern __shared__ ull sh[];
    ull* sIn  = sh;                    // [6][32][61] duplicated {v,v}
    ull* sW   = sh + SIN6_ULL;         // [16][801] packed {w_f0, w_f1}
    ull* sRed = sh + SIN6_ULL + SW_ULL;// [3][128][7]
    __shared__ int sFm[32];
    if (tid < 32) {
        float best = g_s[b*CC + tid]; int wr = 0;
        #pragma unroll
        for (int r = 1; r < 4; r++) {
            float v = g_s[b*CC + r*FM + tid];
            if (v > best) { best = v; wr = r; }
        }
        sFm[tid] = wr*FM + tid;
    }
    __syncthreads();

    for (int idx = tid; idx < 16*800; idx += 512) {
        int fp = idx / 800, rem = idx - fp*800;
        int i = rem / 25, t = rem - i*25;
        float w0 = g_W2[((size_t)sFm[2*fp  ]*CC + sFm[i])*25 + t];
        float w1 = g_W2[((size_t)sFm[2*fp+1]*CC + sFm[i])*25 + t];
        sW[fp*801 + rem] = pack2(w0, w1);
    }

    const float* AbB = g_Ab + (size_t)b*CC*HW;
    int p0 = pg * 7;

    #pragma unroll
    for (int r = 0; r < 5; r++) {
        int row = p0 + r, slot = row % 6, sr = m60(row);
        for (int idx = tid; idx < 32*60; idx += 512) {
            int i = idx / 60, col = idx - i*60;
            float v = AbB[(size_t)sFm[i]*HW + sr*56 + m60(col)];
            sIn[(slot*32 + i)*61 + col] = pack2(v, v);
        }
    }
    __syncthreads();

    const ull* wbase = sW + fl*801;
    int i0 = g*8;

    for (int p = p0; p < p0 + 7; p++) {
        // ---- prefetch padded row p+5 into regs ----
        float pfr[4];
        int prow = p + 5;
        bool pvr = prow < 60;
        int sr = pvr ? m60(prow) : 0;
        #pragma unroll
        for (int j = 0; j < 4; j++) {
            int idx = tid + j*512;
            pfr[j] = 0.f;
            if (pvr && idx < 32*60) {
                int i = idx / 60, col = idx - i*60;
                pfr[j] = AbB[(size_t)sFm[i]*HW + sr*56 + m60(col)];
            }
        }

        // slot base pointers for taps u=0..4 (+ q0 folded in)
        const ull* sb[5];
        #pragma unroll
        for (int u = 0; u < 5; u++)
            sb[u] = sIn + (size_t)((p + u) % 6)*32*61 + q0;

        ull acc[7];
        #pragma unroll
        for (int j = 0; j < 7; j++) acc[j] = 0ull;

        ull wA[5], vA[11], wB[5], vB[11];

        #define LOADW(i_, u_, W) { const ull* _wr = wbase + (i_)*25 + (u_)*5; \
            _Pragma("unroll") for (int _j = 0; _j < 5; _j++) (W)[_j] = _wr[_j]; }
        #define LOADV(i_, u_, V) { const ull* _rp = sb[(u_)] + (i_)*61; \
            _Pragma("unroll") for (int _c = 0; _c < 11; _c++) (V)[_c] = _rp[_c]; }
        #define COMP(W, V) { \
            _Pragma("unroll") for (int _c = 0; _c < 11; _c++) { \
                ull _v = (V)[_c]; \
                if (_c <= 6)             ffma2(acc[_c],   _v, (W)[0]); \
                if (_c >= 1 && _c <= 7)  ffma2(acc[_c-1], _v, (W)[1]); \
                if (_c >= 2 && _c <= 8)  ffma2(acc[_c-2], _v, (W)[2]); \
                if (_c >= 3 && _c <= 9)  ffma2(acc[_c-3], _v, (W)[3]); \
                if (_c >= 4)             ffma2(acc[_c-4], _v, (W)[4]); } }

        LOADW(i0, 0, wA); LOADV(i0, 0, vA);
        #pragma unroll 1
        for (int ii = 0; ii < 8; ii += 2) {
            int i = i0 + ii;
            int inx = (ii == 6) ? i0 : (i + 2);   // dummy-safe final prefetch
            LOADW(i,   1, wB); LOADV(i,   1, vB); COMP(wA, vA);
            LOADW(i,   2, wA); LOADV(i,   2, vA); COMP(wB, vB);
            LOADW(i,   3, wB); LOADV(i,   3, vB); COMP(wA, vA);
            LOADW(i,   4, wA); LOADV(i,   4, vA); COMP(wB, vB);
            LOADW(i+1, 0, wB); LOADV(i+1, 0, vB); COMP(wA, vA);
            LOADW(i+1, 1, wA); LOADV(i+1, 1, vA); COMP(wB, vB);
            LOADW(i+1, 2, wB); LOADV(i+1, 2, vB); COMP(wA, vA);
            LOADW(i+1, 3, wA); LOADV(i+1, 3, vA); COMP(wB, vB);
            LOADW(i+1, 4, wB); LOADV(i+1, 4, vB); COMP(wA, vA);
            LOADW(inx, 0, wA); LOADV(inx, 0, vA); COMP(wB, vB);
        }
        #undef LOADW
        #undef LOADV
        #undef COMP

        // ---- commit prefetched row to slot (p+5)%6 ----
        if (pvr) {
            int slot = prow % 6;
            #pragma unroll
            for (int j = 0; j < 4; j++) {
                int idx = tid + j*512;
                if (idx < 32*60) {
                    int i = idx / 60, col = idx - i*60;
                    sIn[(slot*32 + i)*61 + col] = pack2(pfr[j], pfr[j]);
                }
            }
        }
        // ---- partial handoff: quarters 1..3 write, quarter 0 combines ----
        if (g != 0) {
            ull* red = sRed + (size_t)(g - 1)*128*7 + t7*7;
            #pragma unroll
            for (int j = 0; j < 7; j++) red[j] = acc[j];
        }
        __syncthreads();
        if (g == 0) {
            int f0 = 2*fl, f1 = f0 + 1;
            const float* a0r = AbB + (size_t)sFm[f0]*HW + p*56 + q0;
            const float* a1r = AbB + (size_t)sFm[f1]*HW + p*56 + q0;
            float* o0 = out + ((size_t)(b*FM + f0)*56 + p)*56 + q0;
            float* o1 = out + ((size_t)(b*FM + f1)*56 + p)*56 + q0;
            #pragma unroll
            for (int j = 0; j < 7; j++) {
                float2 v = unpk(acc[j]);
                #pragma unroll
                for (int q = 0; q < 3; q++) {
                    float2 r = unpk(sRed[(size_t)q*128*7 + t7*7 + j]);
                    v.x += r.x; v.y += r.y;
                }
                o0[j] = a0r[j] + THETA_ * (v.x * (1.f/32.f));
                o1[j] = a1r[j] + THETA_ * (v.y * (1.f/32.f));
            }
        }
        __syncthreads();
    }
}

// ---------------- launch ----------------
extern "C" void kernel_launch(void* const* d_in, const int* in_sizes, int n_in,
                              void* d_out, int out_size) {
    const float* A     = (const float*)d_in[0];
    const float* K     = (const float*)d_in[1];
    const float* noise = (const float*)d_in[2];
    float* out = (float*)d_out;

    k_prep<<<BB*CC, 224>>>(A, noise);

    cudaFuncSetAttribute(k_kch, cudaFuncAttributeMaxDynamicSharedMemorySize, SMEM_KCH);
    k_kch<<<dim3(BB, 2, 4), 256, SMEM_KCH>>>();

    k_w2<<<128, 128>>>(K);

    cudaFuncSetAttribute(k_out, cudaFuncAttributeMaxDynamicSharedMemorySize, SMEM_OUT);
    k_out<<<dim3(BB, 8), 512, SMEM_OUT>>>(out);
}